// round 1
// baseline (speedup 1.0000x reference)
#include <cuda_runtime.h>
#include <math.h>

#define NN 50000
#define NE 800000
#define TILE 128
#define SA   164   // e_in row stride (160 cols + pad)
#define SWP  132   // W1 / hidden row stride (128 cols + pad)
#define SW2P 68    // W2 row stride (64 cols + pad)

// ---------------- scratch (static device globals; no allocation) -----------
__device__ float    g_logits[NE];
__device__ float    g_ex[NE];
__device__ float    g_denom[NN];
__device__ unsigned g_maxb[NN];
__device__ float    g_agg[NN * 64];

// ordered-uint encoding of float for atomicMax (monotonic)
__device__ __forceinline__ unsigned ordenc(float f) {
    unsigned u = __float_as_uint(f);
    return (u & 0x80000000u) ? ~u : (u | 0x80000000u);
}
__device__ __forceinline__ float orddec(unsigned u) {
    return __uint_as_float((u & 0x80000000u) ? (u ^ 0x80000000u) : ~u);
}

// ---------------- 8x8 register-tile GEMM microkernel -----------------------
// C[128 rows x 128 cols] += A[128 x K](shared, lda) * B[K x 128](shared, ldb)
// thread (tx,ty) in 16x16 grid owns rows ty*8..+7, cols tx*8..+7
template <int K>
__device__ __forceinline__ void gemm_8x8(const float* __restrict__ sA, int lda,
                                         const float* __restrict__ sB, int ldb,
                                         int tx, int ty, float acc[8][8]) {
#pragma unroll
    for (int i = 0; i < 8; i++)
#pragma unroll
        for (int j = 0; j < 8; j++) acc[i][j] = 0.f;

#pragma unroll 2
    for (int k = 0; k < K; k++) {
        float a[8];
#pragma unroll
        for (int i = 0; i < 8; i++) a[i] = sA[(ty * 8 + i) * lda + k];
        float4 b0 = *(const float4*)(sB + k * ldb + tx * 8);
        float4 b1 = *(const float4*)(sB + k * ldb + tx * 8 + 4);
        float b[8] = {b0.x, b0.y, b0.z, b0.w, b1.x, b1.y, b1.z, b1.w};
#pragma unroll
        for (int i = 0; i < 8; i++)
#pragma unroll
            for (int j = 0; j < 8; j++)
                acc[i][j] = fmaf(a[i], b[j], acc[i][j]);
    }
}

// ---------------- edge kernel: uh_e + attention logits ----------------------
// smem: region1 = e_in [128][SA]; region2 = W1[160][SWP] (aliased by hid[128][SWP]) + W2[128][SW2P]
__global__ void __launch_bounds__(256, 1)
edge_kernel(const float* __restrict__ nf, const float* __restrict__ ef,
            const int* __restrict__ src, const int* __restrict__ dst,
            const float* __restrict__ We1, const float* __restrict__ be1,
            const float* __restrict__ We2, const float* __restrict__ be2,
            const float* __restrict__ Wa1, const float* __restrict__ ba1,
            const float* __restrict__ Wa2, const float* __restrict__ ba2,
            float* __restrict__ uh_e, int E)
{
    extern __shared__ float smem[];
    float* sE   = smem;                    // [128][SA]
    float* sW1  = smem + TILE * SA;        // [160][SWP]
    float* sHid = sW1;                     // [128][SWP] (aliases sW1, used after)
    float* sW2  = sW1 + TILE * SWP;        // [128][SW2P]
    __shared__ int sSrc[TILE], sDst[TILE];

    const int tid = threadIdx.x;
    const int tx = tid & 15, ty = tid >> 4;
    const int e0 = blockIdx.x * TILE;

    if (tid < TILE)            { int e = e0 + tid;          sSrc[tid]        = (e < E) ? src[e] : 0; }
    else if (tid < 2 * TILE)   { int e = e0 + (tid - TILE); sDst[tid - TILE] = (e < E) ? dst[e] : 0; }
    __syncthreads();

    // gather e_in = [nf[src] | nf[dst] | ef] : 40 float4 per edge
    for (int idx = tid; idx < TILE * 40; idx += 256) {
        int le = idx / 40, q = idx - le * 40;
        int e  = e0 + le;
        float4 v = make_float4(0.f, 0.f, 0.f, 0.f);
        if (e < E) {
            if (q < 16)      v = __ldg((const float4*)(nf + (size_t)sSrc[le] * 64) + q);
            else if (q < 32) v = __ldg((const float4*)(nf + (size_t)sDst[le] * 64) + (q - 16));
            else             v = __ldg((const float4*)(ef + (size_t)e * 32) + (q - 32));
        }
        *(float4*)(sE + le * SA + q * 4) = v;
    }
    // stage We1 [160][128]
    for (int idx = tid; idx < 160 * 32; idx += 256) {
        int r = idx >> 5, c4 = idx & 31;
        *(float4*)(sW1 + r * SWP + c4 * 4) = __ldg((const float4*)We1 + idx);
    }
    __syncthreads();

    float acc[8][8];
    gemm_8x8<160>(sE, SA, sW1, SWP, tx, ty, acc);
    __syncthreads();   // all reads of sW1 done before overwriting with hidden

    // relu + bias -> sHid ; stage We2 concurrently
    {
        float4 bb0 = __ldg((const float4*)be1 + tx * 2);
        float4 bb1 = __ldg((const float4*)be1 + tx * 2 + 1);
        float bb[8] = {bb0.x, bb0.y, bb0.z, bb0.w, bb1.x, bb1.y, bb1.z, bb1.w};
#pragma unroll
        for (int i = 0; i < 8; i++)
#pragma unroll
            for (int j = 0; j < 8; j++)
                sHid[(ty * 8 + i) * SWP + tx * 8 + j] = fmaxf(acc[i][j] + bb[j], 0.f);
    }
    for (int idx = tid; idx < 128 * 16; idx += 256) {
        int r = idx >> 4, c4 = idx & 15;
        *(float4*)(sW2 + r * SW2P + c4 * 4) = __ldg((const float4*)We2 + idx);
    }
    __syncthreads();

    // GEMM2: uh_e[128][64] ; thread owns 8 edges x 4 cols
    {
        float acc2[8][4];
#pragma unroll
        for (int i = 0; i < 8; i++)
#pragma unroll
            for (int j = 0; j < 4; j++) acc2[i][j] = 0.f;
#pragma unroll 4
        for (int k = 0; k < 128; k++) {
            float a[8];
#pragma unroll
            for (int i = 0; i < 8; i++) a[i] = sHid[(ty * 8 + i) * SWP + k];
            float4 b = *(const float4*)(sW2 + k * SW2P + tx * 4);
#pragma unroll
            for (int i = 0; i < 8; i++) {
                acc2[i][0] = fmaf(a[i], b.x, acc2[i][0]);
                acc2[i][1] = fmaf(a[i], b.y, acc2[i][1]);
                acc2[i][2] = fmaf(a[i], b.z, acc2[i][2]);
                acc2[i][3] = fmaf(a[i], b.w, acc2[i][3]);
            }
        }
        float4 b2 = __ldg((const float4*)be2 + tx);
#pragma unroll
        for (int i = 0; i < 8; i++) {
            int e = e0 + ty * 8 + i;
            if (e < E) {
                float4 o = make_float4(acc2[i][0] + b2.x, acc2[i][1] + b2.y,
                                       acc2[i][2] + b2.z, acc2[i][3] + b2.w);
                *(float4*)(uh_e + (size_t)e * 64 + tx * 4) = o;
            }
        }
    }
    __syncthreads();   // reads of sHid done before restaging Wa1

    // ---- attention MLP: same e_in tile, Wa1/Wa2 ----
    for (int idx = tid; idx < 160 * 32; idx += 256) {
        int r = idx >> 5, c4 = idx & 31;
        *(float4*)(sW1 + r * SWP + c4 * 4) = __ldg((const float4*)Wa1 + idx);
    }
    __syncthreads();

    gemm_8x8<160>(sE, SA, sW1, SWP, tx, ty, acc);

    // logit = relu(acc + ba1) . Wa2 + ba2 , reduced across the 16 tx lanes
    {
        float4 bb0 = __ldg((const float4*)ba1 + tx * 2);
        float4 bb1 = __ldg((const float4*)ba1 + tx * 2 + 1);
        float4 w0  = __ldg((const float4*)Wa2 + tx * 2);
        float4 w1  = __ldg((const float4*)Wa2 + tx * 2 + 1);
        float bb[8] = {bb0.x, bb0.y, bb0.z, bb0.w, bb1.x, bb1.y, bb1.z, bb1.w};
        float w[8]  = {w0.x, w0.y, w0.z, w0.w, w1.x, w1.y, w1.z, w1.w};
        float b2s = __ldg(ba2);
#pragma unroll
        for (int i = 0; i < 8; i++) {
            float s = 0.f;
#pragma unroll
            for (int j = 0; j < 8; j++)
                s = fmaf(fmaxf(acc[i][j] + bb[j], 0.f), w[j], s);
            // reduce over tx (16 lanes; xor offsets < 16 stay within the group)
            for (int off = 8; off >= 1; off >>= 1)
                s += __shfl_xor_sync(0xffffffffu, s, off);
            if (tx == 0) {
                int e = e0 + ty * 8 + i;
                if (e < E) g_logits[e] = s + b2s;
            }
        }
    }
}

// ---------------- node kernel: uh_n = MLP([agg | nf]) ----------------------
__global__ void __launch_bounds__(256, 1)
node_kernel(const float* __restrict__ nf,
            const float* __restrict__ Wn1, const float* __restrict__ bn1,
            const float* __restrict__ Wn2, const float* __restrict__ bn2,
            float* __restrict__ uh_n, int N)
{
    extern __shared__ float smem[];
    float* sIn  = smem;                    // [128][SWP]
    float* sW1  = smem + TILE * SWP;       // [128][SWP]
    float* sHid = sW1;
    float* sW2  = sW1 + TILE * SWP;        // [128][SW2P]

    const int tid = threadIdx.x;
    const int tx = tid & 15, ty = tid >> 4;
    const int n0 = blockIdx.x * TILE;

    for (int idx = tid; idx < TILE * 32; idx += 256) {
        int ln = idx >> 5, q = idx & 31;
        int n = n0 + ln;
        float4 v = make_float4(0.f, 0.f, 0.f, 0.f);
        if (n < N)
            v = (q < 16) ? __ldg((const float4*)(g_agg + (size_t)n * 64) + q)
                         : __ldg((const float4*)(nf + (size_t)n * 64) + (q - 16));
        *(float4*)(sIn + ln * SWP + q * 4) = v;
    }
    for (int idx = tid; idx < 128 * 32; idx += 256) {
        int r = idx >> 5, c4 = idx & 31;
        *(float4*)(sW1 + r * SWP + c4 * 4) = __ldg((const float4*)Wn1 + idx);
    }
    __syncthreads();

    float acc[8][8];
    gemm_8x8<128>(sIn, SWP, sW1, SWP, tx, ty, acc);
    __syncthreads();

    {
        float4 bb0 = __ldg((const float4*)bn1 + tx * 2);
        float4 bb1 = __ldg((const float4*)bn1 + tx * 2 + 1);
        float bb[8] = {bb0.x, bb0.y, bb0.z, bb0.w, bb1.x, bb1.y, bb1.z, bb1.w};
#pragma unroll
        for (int i = 0; i < 8; i++)
#pragma unroll
            for (int j = 0; j < 8; j++)
                sHid[(ty * 8 + i) * SWP + tx * 8 + j] = fmaxf(acc[i][j] + bb[j], 0.f);
    }
    for (int idx = tid; idx < 128 * 16; idx += 256) {
        int r = idx >> 4, c4 = idx & 15;
        *(float4*)(sW2 + r * SW2P + c4 * 4) = __ldg((const float4*)Wn2 + idx);
    }
    __syncthreads();

    {
        float acc2[8][4];
#pragma unroll
        for (int i = 0; i < 8; i++)
#pragma unroll
            for (int j = 0; j < 4; j++) acc2[i][j] = 0.f;
#pragma unroll 4
        for (int k = 0; k < 128; k++) {
            float a[8];
#pragma unroll
            for (int i = 0; i < 8; i++) a[i] = sHid[(ty * 8 + i) * SWP + k];
            float4 b = *(const float4*)(sW2 + k * SW2P + tx * 4);
#pragma unroll
            for (int i = 0; i < 8; i++) {
                acc2[i][0] = fmaf(a[i], b.x, acc2[i][0]);
                acc2[i][1] = fmaf(a[i], b.y, acc2[i][1]);
                acc2[i][2] = fmaf(a[i], b.z, acc2[i][2]);
                acc2[i][3] = fmaf(a[i], b.w, acc2[i][3]);
            }
        }
        float4 b2 = __ldg((const float4*)bn2 + tx);
#pragma unroll
        for (int i = 0; i < 8; i++) {
            int n = n0 + ty * 8 + i;
            if (n < N) {
                float4 o = make_float4(acc2[i][0] + b2.x, acc2[i][1] + b2.y,
                                       acc2[i][2] + b2.z, acc2[i][3] + b2.w);
                *(float4*)(uh_n + (size_t)n * 64 + tx * 4) = o;
            }
        }
    }
}

// ---------------- softmax / aggregation kernels -----------------------------
__global__ void init_kernel(int N) {
    int t = blockIdx.x * blockDim.x + threadIdx.x;
    if (t < N * 64) g_agg[t] = 0.f;
    if (t < N) { g_denom[t] = 0.f; g_maxb[t] = 0u; }
}

__global__ void max_kernel(const int* __restrict__ dst, int E) {
    int t = blockIdx.x * blockDim.x + threadIdx.x;
    if (t < E) atomicMax(&g_maxb[dst[t]], ordenc(g_logits[t]));
}

__global__ void ex_kernel(const int* __restrict__ dst, int E) {
    int t = blockIdx.x * blockDim.x + threadIdx.x;
    if (t < E) {
        int d = dst[t];
        float m = orddec(g_maxb[d]);
        if (!isfinite(m)) m = 0.f;
        float ex = expf(g_logits[t] - m);
        g_ex[t] = ex;
        atomicAdd(&g_denom[d], ex);
    }
}

__global__ void agg_kernel(const int* __restrict__ dst, const float* __restrict__ uh_e, int E) {
    int t = blockIdx.x * blockDim.x + threadIdx.x;
    int e = t >> 4, lane = t & 15;
    if (e < E) {
        int d = dst[e];
        float attn = g_ex[e] / fmaxf(g_denom[d], 1e-38f);
        float4 u = __ldg((const float4*)(uh_e + (size_t)e * 64) + lane);
        float* p = g_agg + (size_t)d * 64 + lane * 4;
        atomicAdd(p + 0, u.x * attn);
        atomicAdd(p + 1, u.y * attn);
        atomicAdd(p + 2, u.z * attn);
        atomicAdd(p + 3, u.w * attn);
    }
}

// ---------------- launch -----------------------------------------------------
extern "C" void kernel_launch(void* const* d_in, const int* in_sizes, int n_in,
                              void* d_out, int out_size)
{
    const float* nf  = (const float*)d_in[0];
    const float* ef  = (const float*)d_in[1];
    const int*   src = (const int*)d_in[2];
    const int*   dst = (const int*)d_in[3];
    const float* We1 = (const float*)d_in[4];
    const float* be1 = (const float*)d_in[5];
    const float* We2 = (const float*)d_in[6];
    const float* be2 = (const float*)d_in[7];
    const float* Wa1 = (const float*)d_in[8];
    const float* ba1 = (const float*)d_in[9];
    const float* Wa2 = (const float*)d_in[10];
    const float* ba2 = (const float*)d_in[11];
    const float* Wn1 = (const float*)d_in[12];
    const float* bn1 = (const float*)d_in[13];
    const float* Wn2 = (const float*)d_in[14];
    const float* bn2 = (const float*)d_in[15];

    const int N = in_sizes[0] / 64;
    const int E = in_sizes[2];

    float* uh_n = (float*)d_out;            // [N, 64]
    float* uh_e = uh_n + (size_t)N * 64;    // [E, 64]

    const int EDGE_SMEM = (TILE * SA + TILE * SWP + TILE * SW2P) * (int)sizeof(float);   // 186368
    const int NODE_SMEM = (TILE * SWP * 2 + TILE * SW2P) * (int)sizeof(float);           // 169984

    cudaFuncSetAttribute(edge_kernel, cudaFuncAttributeMaxDynamicSharedMemorySize, EDGE_SMEM);
    cudaFuncSetAttribute(node_kernel, cudaFuncAttributeMaxDynamicSharedMemorySize, NODE_SMEM);

    init_kernel<<<(N * 64 + 255) / 256, 256>>>(N);
    edge_kernel<<<(E + TILE - 1) / TILE, 256, EDGE_SMEM>>>(
        nf, ef, src, dst, We1, be1, We2, be2, Wa1, ba1, Wa2, ba2, uh_e, E);
    max_kernel<<<(E + 255) / 256, 256>>>(dst, E);
    ex_kernel<<<(E + 255) / 256, 256>>>(dst, E);
    agg_kernel<<<(int)(((size_t)E * 16 + 255) / 256), 256>>>(dst, uh_e, E);
    node_kernel<<<(N + TILE - 1) / TILE, 256, NODE_SMEM>>>(
        nf, Wn1, bn1, Wn2, bn2, uh_n, N);
}

// round 2
// speedup vs baseline: 1.3062x; 1.3062x over previous
#include <cuda_runtime.h>
#include <math.h>

#define NN 50000
#define NE 800000
#define SA 164     // e_in / hidden row stride in smem (≡4 mod 32: conflict-free frags)

// ---------------- scratch (static device globals; no allocation) -----------
__device__ float    g_logits[NE];
__device__ float    g_ex[NE];
__device__ float    g_denom[NN];
__device__ unsigned g_maxb[NN];
__device__ float    g_agg[NN * 64];

// tf32 fragment-layout weights (filled by prep_kernel each launch)
__device__ float4 g_We1f[20 * 16 * 64 / 4];   // [kk=20][nb=16][lane=32][slot=2]
__device__ float4 g_Wa1f[20 * 16 * 64 / 4];
__device__ float4 g_We2f[16 * 8 * 64 / 4];    // [kk=16][nb=8][lane=32][slot=2]

__device__ __forceinline__ unsigned ordenc(float f) {
    unsigned u = __float_as_uint(f);
    return (u & 0x80000000u) ? ~u : (u | 0x80000000u);
}
__device__ __forceinline__ float orddec(unsigned u) {
    return __uint_as_float((u & 0x80000000u) ? (u ^ 0x80000000u) : ~u);
}

__device__ __forceinline__ unsigned to_tf32_bits(float x) {
    unsigned r;
    asm("cvt.rna.tf32.f32 %0, %1;" : "=r"(r) : "f"(x));
    return r;
}
__device__ __forceinline__ float to_tf32(float x) {
    return __uint_as_float(to_tf32_bits(x));
}

__device__ __forceinline__ void mma_tf32(float c[4], const unsigned a[4],
                                         unsigned b0, unsigned b1) {
    asm volatile(
        "mma.sync.aligned.m16n8k8.row.col.f32.tf32.tf32.f32 "
        "{%0,%1,%2,%3},{%4,%5,%6,%7},{%8,%9},{%0,%1,%2,%3};\n"
        : "+f"(c[0]), "+f"(c[1]), "+f"(c[2]), "+f"(c[3])
        : "r"(a[0]), "r"(a[1]), "r"(a[2]), "r"(a[3]), "r"(b0), "r"(b1));
}

// ---------------- weight prep: fp32 row-major -> tf32 fragment layout -------
__global__ void prep_kernel(const float* __restrict__ We1,
                            const float* __restrict__ Wa1,
                            const float* __restrict__ We2) {
    int idx = blockIdx.x * blockDim.x + threadIdx.x;
    if (idx < 20480) {                          // W1-type: [160][128]
        int k = idx >> 7, n = idx & 127;
        int kk = k >> 3, kr = k & 7, slot = kr >> 2, t = kr & 3;
        int nb = n >> 3, g = n & 7;
        int d = ((kk * 16 + nb) * 32 + (g * 4 + t)) * 2 + slot;
        ((float*)g_We1f)[d] = to_tf32(We1[idx]);
        ((float*)g_Wa1f)[d] = to_tf32(Wa1[idx]);
    } else if (idx < 20480 + 8192) {            // W2: [128][64]
        int i = idx - 20480;
        int k = i >> 6, n = i & 63;
        int kk = k >> 3, kr = k & 7, slot = kr >> 2, t = kr & 3;
        int nb = n >> 3, g = n & 7;
        int d = ((kk * 8 + nb) * 32 + (g * 4 + t)) * 2 + slot;
        ((float*)g_We2f)[d] = to_tf32(We2[i]);
    }
}

// ---------------- edge kernel: tensor-core MLPs + attention logits ----------
// block = 128 edges, 256 threads (8 warps: warp_m = wid&3, warp_n = wid>>2)
__global__ void __launch_bounds__(256, 1)
edge_kernel(const float* __restrict__ nf, const float* __restrict__ ef,
            const int* __restrict__ src, const int* __restrict__ dst,
            const float* __restrict__ be1, const float* __restrict__ be2,
            const float* __restrict__ ba1, const float* __restrict__ Wa2,
            const float* __restrict__ ba2,
            float* __restrict__ uh_e, int E)
{
    extern __shared__ float smem[];
    float* sA = smem;                 // [128][SA] e_in tf32; later hidden tf32
    float* sW = smem + 128 * SA;      // 20480 floats: frag weights (W1 then W2)
    __shared__ float sLogit[2][128];
    __shared__ int sSrc[128], sDst[128];

    const int tid  = threadIdx.x;
    const int lane = tid & 31, wid = tid >> 5;
    const int g = lane >> 2, t = lane & 3;
    const int warp_m = wid & 3, warp_n = wid >> 2;
    const int e0 = blockIdx.x * 128;

    if (tid < 128)      { int e = e0 + tid;       sSrc[tid]       = (e < E) ? src[e] : 0; }
    else                { int e = e0 + tid - 128; sDst[tid - 128] = (e < E) ? dst[e] : 0; }
    // stage We1 frags (coalesced float4 copy)
    for (int i = tid; i < 5120; i += 256) ((float4*)sW)[i] = g_We1f[i];
    __syncthreads();

    // gather e_in = [nf[src] | nf[dst] | ef], convert to tf32
    for (int idx = tid; idx < 128 * 40; idx += 256) {
        int le = idx / 40, q = idx - le * 40;
        int e = e0 + le;
        float4 v = make_float4(0.f, 0.f, 0.f, 0.f);
        if (e < E) {
            if (q < 16)      v = __ldg((const float4*)(nf + (size_t)sSrc[le] * 64) + q);
            else if (q < 32) v = __ldg((const float4*)(nf + (size_t)sDst[le] * 64) + (q - 16));
            else             v = __ldg((const float4*)(ef + (size_t)e * 32) + (q - 32));
        }
        v.x = to_tf32(v.x); v.y = to_tf32(v.y); v.z = to_tf32(v.z); v.w = to_tf32(v.w);
        *(float4*)(sA + le * SA + q * 4) = v;
    }
    __syncthreads();

    const unsigned* sAu = (const unsigned*)sA;
    const uint2*    sWu = (const uint2*)sW;

    // ---- GEMM1 (edge MLP layer 1): [128x160] x [160x128] ----
    float accE[2][8][4];
#pragma unroll
    for (int mt = 0; mt < 2; mt++)
#pragma unroll
        for (int nb = 0; nb < 8; nb++)
#pragma unroll
            for (int q = 0; q < 4; q++) accE[mt][nb][q] = 0.f;
    {
        unsigned a[2][4];
#pragma unroll 4
        for (int kk = 0; kk < 20; kk++) {
            int col = kk * 8 + t;
#pragma unroll
            for (int mt = 0; mt < 2; mt++) {
                int row = warp_m * 32 + mt * 16 + g;
                a[mt][0] = sAu[row * SA + col];
                a[mt][1] = sAu[(row + 8) * SA + col];
                a[mt][2] = sAu[row * SA + col + 4];
                a[mt][3] = sAu[(row + 8) * SA + col + 4];
            }
#pragma unroll
            for (int nb = 0; nb < 8; nb++) {
                uint2 b = sWu[(kk * 16 + warp_n * 8 + nb) * 32 + lane];
                mma_tf32(accE[0][nb], a[0], b.x, b.y);
                mma_tf32(accE[1][nb], a[1], b.x, b.y);
            }
        }
    }
    __syncthreads();
    // restage Wa1 frags
    for (int i = tid; i < 5120; i += 256) ((float4*)sW)[i] = g_Wa1f[i];
    __syncthreads();

    // ---- GEMM1 (attention layer 1) ----
    float accA[2][8][4];
#pragma unroll
    for (int mt = 0; mt < 2; mt++)
#pragma unroll
        for (int nb = 0; nb < 8; nb++)
#pragma unroll
            for (int q = 0; q < 4; q++) accA[mt][nb][q] = 0.f;
    {
        unsigned a[2][4];
#pragma unroll 4
        for (int kk = 0; kk < 20; kk++) {
            int col = kk * 8 + t;
#pragma unroll
            for (int mt = 0; mt < 2; mt++) {
                int row = warp_m * 32 + mt * 16 + g;
                a[mt][0] = sAu[row * SA + col];
                a[mt][1] = sAu[(row + 8) * SA + col];
                a[mt][2] = sAu[row * SA + col + 4];
                a[mt][3] = sAu[(row + 8) * SA + col + 4];
            }
#pragma unroll
            for (int nb = 0; nb < 8; nb++) {
                uint2 b = sWu[(kk * 16 + warp_n * 8 + nb) * 32 + lane];
                mma_tf32(accA[0][nb], a[0], b.x, b.y);
                mma_tf32(accA[1][nb], a[1], b.x, b.y);
            }
        }
    }

    // ---- attention epilogue: logit = relu(h)·Wa2 + ba2 (in registers) ----
    {
        float p00 = 0.f, p10 = 0.f, p01 = 0.f, p11 = 0.f;
#pragma unroll
        for (int nb = 0; nb < 8; nb++) {
            int col = warp_n * 64 + nb * 8 + 2 * t;
            float b0 = __ldg(ba1 + col), b1 = __ldg(ba1 + col + 1);
            float w0 = __ldg(Wa2 + col), w1 = __ldg(Wa2 + col + 1);
            p00 += fmaxf(accA[0][nb][0] + b0, 0.f) * w0 + fmaxf(accA[0][nb][1] + b1, 0.f) * w1;
            p10 += fmaxf(accA[0][nb][2] + b0, 0.f) * w0 + fmaxf(accA[0][nb][3] + b1, 0.f) * w1;
            p01 += fmaxf(accA[1][nb][0] + b0, 0.f) * w0 + fmaxf(accA[1][nb][1] + b1, 0.f) * w1;
            p11 += fmaxf(accA[1][nb][2] + b0, 0.f) * w0 + fmaxf(accA[1][nb][3] + b1, 0.f) * w1;
        }
#pragma unroll
        for (int off = 1; off <= 2; off <<= 1) {
            p00 += __shfl_xor_sync(0xffffffffu, p00, off);
            p10 += __shfl_xor_sync(0xffffffffu, p10, off);
            p01 += __shfl_xor_sync(0xffffffffu, p01, off);
            p11 += __shfl_xor_sync(0xffffffffu, p11, off);
        }
        if (t == 0) {
            sLogit[warp_n][warp_m * 32 + g]      = p00;
            sLogit[warp_n][warp_m * 32 + 8 + g]  = p10;
            sLogit[warp_n][warp_m * 32 + 16 + g] = p01;
            sLogit[warp_n][warp_m * 32 + 24 + g] = p11;
        }
    }
    __syncthreads();   // sLogit ready; all reads of sA / sW done

    if (tid < 128) {
        int e = e0 + tid;
        if (e < E) g_logits[e] = sLogit[0][tid] + sLogit[1][tid] + __ldg(ba2);
    }

    // ---- hidden (edge) -> sA region (tf32), stage We2 frags ----
#pragma unroll
    for (int mt = 0; mt < 2; mt++)
#pragma unroll
        for (int nb = 0; nb < 8; nb++) {
            int col = warp_n * 64 + nb * 8 + 2 * t;
            float b0 = __ldg(be1 + col), b1 = __ldg(be1 + col + 1);
            int r0 = warp_m * 32 + mt * 16 + g;
            sA[r0 * SA + col]           = to_tf32(fmaxf(accE[mt][nb][0] + b0, 0.f));
            sA[r0 * SA + col + 1]       = to_tf32(fmaxf(accE[mt][nb][1] + b1, 0.f));
            sA[(r0 + 8) * SA + col]     = to_tf32(fmaxf(accE[mt][nb][2] + b0, 0.f));
            sA[(r0 + 8) * SA + col + 1] = to_tf32(fmaxf(accE[mt][nb][3] + b1, 0.f));
        }
    for (int i = tid; i < 2048; i += 256) ((float4*)sW)[i] = g_We2f[i];
    __syncthreads();

    // ---- GEMM2 (edge MLP layer 2): [128x128] x [128x64] ----
    {
        float accO[2][4][4];
#pragma unroll
        for (int mt = 0; mt < 2; mt++)
#pragma unroll
            for (int nb = 0; nb < 4; nb++)
#pragma unroll
                for (int q = 0; q < 4; q++) accO[mt][nb][q] = 0.f;
        unsigned a[2][4];
#pragma unroll 4
        for (int kk = 0; kk < 16; kk++) {
            int col = kk * 8 + t;
#pragma unroll
            for (int mt = 0; mt < 2; mt++) {
                int row = warp_m * 32 + mt * 16 + g;
                a[mt][0] = sAu[row * SA + col];
                a[mt][1] = sAu[(row + 8) * SA + col];
                a[mt][2] = sAu[row * SA + col + 4];
                a[mt][3] = sAu[(row + 8) * SA + col + 4];
            }
#pragma unroll
            for (int nb = 0; nb < 4; nb++) {
                uint2 b = sWu[(kk * 8 + warp_n * 4 + nb) * 32 + lane];
                mma_tf32(accO[0][nb], a[0], b.x, b.y);
                mma_tf32(accO[1][nb], a[1], b.x, b.y);
            }
        }
        // epilogue: + be2, store uh_e
#pragma unroll
        for (int mt = 0; mt < 2; mt++)
#pragma unroll
            for (int nb = 0; nb < 4; nb++) {
                int col = warp_n * 32 + nb * 8 + 2 * t;
                float b0 = __ldg(be2 + col), b1 = __ldg(be2 + col + 1);
                int r0 = warp_m * 32 + mt * 16 + g;
                int e = e0 + r0;
                if (e < E) {
                    float2 o0 = make_float2(accO[mt][nb][0] + b0, accO[mt][nb][1] + b1);
                    *(float2*)(uh_e + (size_t)e * 64 + col) = o0;
                }
                if (e + 8 < E) {
                    float2 o1 = make_float2(accO[mt][nb][2] + b0, accO[mt][nb][3] + b1);
                    *(float2*)(uh_e + (size_t)(e + 8) * 64 + col) = o1;
                }
            }
    }
}

// ---------------- node kernel (fp32, unchanged from R1) ---------------------
#define TILE 128
#define SWP  132
#define SW2P 68
template <int K>
__device__ __forceinline__ void gemm_8x8(const float* __restrict__ sAm, int lda,
                                         const float* __restrict__ sB, int ldb,
                                         int tx, int ty, float acc[8][8]) {
#pragma unroll
    for (int i = 0; i < 8; i++)
#pragma unroll
        for (int j = 0; j < 8; j++) acc[i][j] = 0.f;
#pragma unroll 2
    for (int k = 0; k < K; k++) {
        float a[8];
#pragma unroll
        for (int i = 0; i < 8; i++) a[i] = sAm[(ty * 8 + i) * lda + k];
        float4 b0 = *(const float4*)(sB + k * ldb + tx * 8);
        float4 b1 = *(const float4*)(sB + k * ldb + tx * 8 + 4);
        float b[8] = {b0.x, b0.y, b0.z, b0.w, b1.x, b1.y, b1.z, b1.w};
#pragma unroll
        for (int i = 0; i < 8; i++)
#pragma unroll
            for (int j = 0; j < 8; j++)
                acc[i][j] = fmaf(a[i], b[j], acc[i][j]);
    }
}

__global__ void __launch_bounds__(256, 1)
node_kernel(const float* __restrict__ nf,
            const float* __restrict__ Wn1, const float* __restrict__ bn1,
            const float* __restrict__ Wn2, const float* __restrict__ bn2,
            float* __restrict__ uh_n, int N)
{
    extern __shared__ float smem[];
    float* sIn  = smem;
    float* sW1  = smem + TILE * SWP;
    float* sHid = sW1;
    float* sW2  = sW1 + TILE * SWP;

    const int tid = threadIdx.x;
    const int tx = tid & 15, ty = tid >> 4;
    const int n0 = blockIdx.x * TILE;

    for (int idx = tid; idx < TILE * 32; idx += 256) {
        int ln = idx >> 5, q = idx & 31;
        int n = n0 + ln;
        float4 v = make_float4(0.f, 0.f, 0.f, 0.f);
        if (n < N)
            v = (q < 16) ? __ldg((const float4*)(g_agg + (size_t)n * 64) + q)
                         : __ldg((const float4*)(nf + (size_t)n * 64) + (q - 16));
        *(float4*)(sIn + ln * SWP + q * 4) = v;
    }
    for (int idx = tid; idx < 128 * 32; idx += 256) {
        int r = idx >> 5, c4 = idx & 31;
        *(float4*)(sW1 + r * SWP + c4 * 4) = __ldg((const float4*)Wn1 + idx);
    }
    __syncthreads();

    float acc[8][8];
    gemm_8x8<128>(sIn, SWP, sW1, SWP, tx, ty, acc);
    __syncthreads();

    {
        float4 bb0 = __ldg((const float4*)bn1 + tx * 2);
        float4 bb1 = __ldg((const float4*)bn1 + tx * 2 + 1);
        float bb[8] = {bb0.x, bb0.y, bb0.z, bb0.w, bb1.x, bb1.y, bb1.z, bb1.w};
#pragma unroll
        for (int i = 0; i < 8; i++)
#pragma unroll
            for (int j = 0; j < 8; j++)
                sHid[(ty * 8 + i) * SWP + tx * 8 + j] = fmaxf(acc[i][j] + bb[j], 0.f);
    }
    for (int idx = tid; idx < 128 * 16; idx += 256) {
        int r = idx >> 4, c4 = idx & 15;
        *(float4*)(sW2 + r * SW2P + c4 * 4) = __ldg((const float4*)Wn2 + idx);
    }
    __syncthreads();

    {
        float acc2[8][4];
#pragma unroll
        for (int i = 0; i < 8; i++)
#pragma unroll
            for (int j = 0; j < 4; j++) acc2[i][j] = 0.f;
#pragma unroll 4
        for (int k = 0; k < 128; k++) {
            float a[8];
#pragma unroll
            for (int i = 0; i < 8; i++) a[i] = sHid[(ty * 8 + i) * SWP + k];
            float4 b = *(const float4*)(sW2 + k * SW2P + tx * 4);
#pragma unroll
            for (int i = 0; i < 8; i++) {
                acc2[i][0] = fmaf(a[i], b.x, acc2[i][0]);
                acc2[i][1] = fmaf(a[i], b.y, acc2[i][1]);
                acc2[i][2] = fmaf(a[i], b.z, acc2[i][2]);
                acc2[i][3] = fmaf(a[i], b.w, acc2[i][3]);
            }
        }
        float4 b2 = __ldg((const float4*)bn2 + tx);
#pragma unroll
        for (int i = 0; i < 8; i++) {
            int n = n0 + ty * 8 + i;
            if (n < N) {
                float4 o = make_float4(acc2[i][0] + b2.x, acc2[i][1] + b2.y,
                                       acc2[i][2] + b2.z, acc2[i][3] + b2.w);
                *(float4*)(uh_n + (size_t)n * 64 + tx * 4) = o;
            }
        }
    }
}

// ---------------- softmax / aggregation kernels -----------------------------
__global__ void init_kernel(int N) {
    int t = blockIdx.x * blockDim.x + threadIdx.x;
    if (t < N * 64) g_agg[t] = 0.f;
    if (t < N) { g_denom[t] = 0.f; g_maxb[t] = 0u; }
}
__global__ void max_kernel(const int* __restrict__ dst, int E) {
    int t = blockIdx.x * blockDim.x + threadIdx.x;
    if (t < E) atomicMax(&g_maxb[dst[t]], ordenc(g_logits[t]));
}
__global__ void ex_kernel(const int* __restrict__ dst, int E) {
    int t = blockIdx.x * blockDim.x + threadIdx.x;
    if (t < E) {
        int d = dst[t];
        float m = orddec(g_maxb[d]);
        if (!isfinite(m)) m = 0.f;
        float ex = expf(g_logits[t] - m);
        g_ex[t] = ex;
        atomicAdd(&g_denom[d], ex);
    }
}
__global__ void agg_kernel(const int* __restrict__ dst, const float* __restrict__ uh_e, int E) {
    int t = blockIdx.x * blockDim.x + threadIdx.x;
    int e = t >> 4, lane = t & 15;
    if (e < E) {
        int d = dst[e];
        float attn = g_ex[e] / fmaxf(g_denom[d], 1e-38f);
        float4 u = __ldg((const float4*)(uh_e + (size_t)e * 64) + lane);
        float* p = g_agg + (size_t)d * 64 + lane * 4;
        atomicAdd(p + 0, u.x * attn);
        atomicAdd(p + 1, u.y * attn);
        atomicAdd(p + 2, u.z * attn);
        atomicAdd(p + 3, u.w * attn);
    }
}

// ---------------- launch -----------------------------------------------------
extern "C" void kernel_launch(void* const* d_in, const int* in_sizes, int n_in,
                              void* d_out, int out_size)
{
    const float* nf  = (const float*)d_in[0];
    const float* ef  = (const float*)d_in[1];
    const int*   src = (const int*)d_in[2];
    const int*   dst = (const int*)d_in[3];
    const float* We1 = (const float*)d_in[4];
    const float* be1 = (const float*)d_in[5];
    const float* We2 = (const float*)d_in[6];
    const float* be2 = (const float*)d_in[7];
    const float* Wa1 = (const float*)d_in[8];
    const float* ba1 = (const float*)d_in[9];
    const float* Wa2 = (const float*)d_in[10];
    const float* ba2 = (const float*)d_in[11];
    const float* Wn1 = (const float*)d_in[12];
    const float* bn1 = (const float*)d_in[13];
    const float* Wn2 = (const float*)d_in[14];
    const float* bn2 = (const float*)d_in[15];

    const int N = in_sizes[0] / 64;
    const int E = in_sizes[2];

    float* uh_n = (float*)d_out;
    float* uh_e = uh_n + (size_t)N * 64;

    const int EDGE_SMEM = (128 * SA + 20480) * (int)sizeof(float);               // 165888
    const int NODE_SMEM = (TILE * SWP * 2 + TILE * SW2P) * (int)sizeof(float);   // 169984

    cudaFuncSetAttribute(edge_kernel, cudaFuncAttributeMaxDynamicSharedMemorySize, EDGE_SMEM);
    cudaFuncSetAttribute(node_kernel, cudaFuncAttributeMaxDynamicSharedMemorySize, NODE_SMEM);

    prep_kernel<<<(20480 + 8192 + 255) / 256, 256>>>(We1, Wa1, We2);
    init_kernel<<<(N * 64 + 255) / 256, 256>>>(N);
    edge_kernel<<<(E + 127) / 128, 256, EDGE_SMEM>>>(
        nf, ef, src, dst, be1, be2, ba1, Wa2, ba2, uh_e, E);
    max_kernel<<<(E + 255) / 256, 256>>>(dst, E);
    ex_kernel<<<(E + 255) / 256, 256>>>(dst, E);
    agg_kernel<<<(int)(((size_t)E * 16 + 255) / 256), 256>>>(dst, uh_e, E);
    node_kernel<<<(N + TILE - 1) / TILE, 256, NODE_SMEM>>>(
        nf, Wn1, bn1, Wn2, bn2, uh_n, N);
}

// round 5
// speedup vs baseline: 2.3654x; 1.8110x over previous
#include <cuda_runtime.h>
#include <cuda_fp16.h>
#include <math.h>
#include <stdint.h>

#define NN 50000
#define NE 800000
#define SA2 168    // A-tile row stride in fp16 units (168*2=336B: conflict-free frags)

// ---------------- scratch (static device globals; no allocation) -----------
__device__ float    g_logits[NE];
__device__ float    g_ex[NE];
__device__ float    g_denom[NN];
__device__ unsigned g_maxb[NN];
__device__ float    g_agg[NN * 64];

// fp16 fragment-packed weights (filled once per launch by prep_kernel)
// W1 (160x128): frag (kk=10, nbt=16, lane=32, reg=2) ; W2 (128x64): (8, 8, 32, 2)
__device__ unsigned g_W1e[10240];
__device__ unsigned g_W1a[10240];
__device__ unsigned g_W2e[4096];

__device__ __forceinline__ unsigned ordenc(float f) {
    unsigned u = __float_as_uint(f);
    return (u & 0x80000000u) ? ~u : (u | 0x80000000u);
}
__device__ __forceinline__ float orddec(unsigned u) {
    return __uint_as_float((u & 0x80000000u) ? (u ^ 0x80000000u) : ~u);
}
__device__ __forceinline__ unsigned pack_h2(float a, float b) {
    __half2 h = __floats2half2_rn(a, b);
    return *(unsigned*)&h;
}

__device__ __forceinline__ void mma_f16(float c[4], const unsigned a[4], uint2 b) {
    asm volatile(
        "mma.sync.aligned.m16n8k16.row.col.f32.f16.f16.f32 "
        "{%0,%1,%2,%3},{%4,%5,%6,%7},{%8,%9},{%0,%1,%2,%3};\n"
        : "+f"(c[0]), "+f"(c[1]), "+f"(c[2]), "+f"(c[3])
        : "r"(a[0]), "r"(a[1]), "r"(a[2]), "r"(a[3]), "r"(b.x), "r"(b.y));
}

// ---------------- weight prep: fp32 row-major -> fp16 fragment pairs --------
__global__ void prep_kernel(const float* __restrict__ We1,
                            const float* __restrict__ Wa1,
                            const float* __restrict__ We2) {
    int idx = blockIdx.x * blockDim.x + threadIdx.x;
    if (idx < 10240) {                      // W1-type [K=160][N=128]
        int reg = idx & 1, lane = (idx >> 1) & 31, nbt = (idx >> 6) & 15, kk = idx >> 10;
        int g = lane >> 2, t = lane & 3;
        int n = nbt * 8 + g;
        int k0 = kk * 16 + 2 * t + reg * 8;
        g_W1e[idx] = pack_h2(We1[k0 * 128 + n], We1[(k0 + 1) * 128 + n]);
        g_W1a[idx] = pack_h2(Wa1[k0 * 128 + n], Wa1[(k0 + 1) * 128 + n]);
    } else if (idx < 10240 + 4096) {        // W2 [K=128][N=64]
        int i = idx - 10240;
        int reg = i & 1, lane = (i >> 1) & 31, nbt = (i >> 6) & 7, kk = i >> 9;
        int g = lane >> 2, t = lane & 3;
        int n = nbt * 8 + g;
        int k0 = kk * 16 + 2 * t + reg * 8;
        g_W2e[i] = pack_h2(We2[k0 * 64 + n], We2[(k0 + 1) * 64 + n]);
    }
}

// ---------------- edge kernel: fp16 HMMA MLPs + attention logits ------------
// block = 128 edges, 256 threads; warp_m = wid&3 (rows), warp_n = wid>>2 (cols)
#define A_BYTES (128 * SA2 * 2)      // 43008
#define W_UINTS 10240                // W1 frag buffer (40960 B)

__global__ void __launch_bounds__(256, 1)
edge_kernel(const float* __restrict__ nf, const float* __restrict__ ef,
            const int* __restrict__ src, const int* __restrict__ dst,
            const float* __restrict__ be1, const float* __restrict__ be2,
            const float* __restrict__ ba1, const float* __restrict__ Wa2,
            const float* __restrict__ ba2,
            float* __restrict__ uh_e, int E)
{
    extern __shared__ __align__(16) char dyn[];
    char* pA = dyn;                               // A tile: fp16 [128][SA2]
    unsigned* sW = (unsigned*)(dyn + A_BYTES);    // weight frags
    __shared__ float sLogit[2][128];
    __shared__ int sSrc[128], sDst[128];

    const int tid = threadIdx.x;
    const int lane = tid & 31, wid = tid >> 5;
    const int g = lane >> 2, t = lane & 3;
    const int warp_m = wid & 3, warp_n = wid >> 2;
    const int e0 = blockIdx.x * 128;

    if (tid < 128)      { int e = e0 + tid;       sSrc[tid]       = (e < E) ? src[e] : 0; }
    else                { int e = e0 + tid - 128; sDst[tid - 128] = (e < E) ? dst[e] : 0; }
    // stage We1 frags
    for (int i = tid; i < W_UINTS / 4; i += 256) ((uint4*)sW)[i] = ((const uint4*)g_W1e)[i];
    __syncthreads();

    // gather e_in = [nf[src] | nf[dst] | ef] -> fp16 tile
    for (int idx = tid; idx < 128 * 40; idx += 256) {
        int le = idx / 40, q = idx - le * 40;
        int e = e0 + le;
        float4 v = make_float4(0.f, 0.f, 0.f, 0.f);
        if (e < E) {
            if (q < 16)      v = __ldg((const float4*)(nf + (size_t)sSrc[le] * 64) + q);
            else if (q < 32) v = __ldg((const float4*)(nf + (size_t)sDst[le] * 64) + (q - 16));
            else             v = __ldg((const float4*)(ef + (size_t)e * 32) + (q - 32));
        }
        uint2 o = make_uint2(pack_h2(v.x, v.y), pack_h2(v.z, v.w));
        *(uint2*)(pA + le * (SA2 * 2) + q * 8) = o;
    }
    __syncthreads();

    const uint2* sWu = (const uint2*)sW;

    // ---- GEMM1-edge: [128x160] x We1 -> accE ----
    float accE[2][8][4];
#pragma unroll
    for (int mt = 0; mt < 2; mt++)
#pragma unroll
        for (int nb = 0; nb < 8; nb++)
#pragma unroll
            for (int q = 0; q < 4; q++) accE[mt][nb][q] = 0.f;
    {
        unsigned a[2][4];
#pragma unroll
        for (int kk = 0; kk < 10; kk++) {
#pragma unroll
            for (int mt = 0; mt < 2; mt++) {
                int row = warp_m * 32 + mt * 16 + g;
                const char* base = pA + row * (SA2 * 2) + kk * 32 + 4 * t;
                a[mt][0] = *(const unsigned*)(base);
                a[mt][1] = *(const unsigned*)(base + 8 * (SA2 * 2));
                a[mt][2] = *(const unsigned*)(base + 16);
                a[mt][3] = *(const unsigned*)(base + 8 * (SA2 * 2) + 16);
            }
#pragma unroll
            for (int nb = 0; nb < 8; nb++) {
                uint2 b = sWu[(kk * 16 + warp_n * 8 + nb) * 32 + lane];
                mma_f16(accE[0][nb], a[0], b);
                mma_f16(accE[1][nb], a[1], b);
            }
        }
    }
    __syncthreads();
    // restage Wa1 frags
    for (int i = tid; i < W_UINTS / 4; i += 256) ((uint4*)sW)[i] = ((const uint4*)g_W1a)[i];
    __syncthreads();

    // ---- GEMM1-attn ----
    float accA[2][8][4];
#pragma unroll
    for (int mt = 0; mt < 2; mt++)
#pragma unroll
        for (int nb = 0; nb < 8; nb++)
#pragma unroll
            for (int q = 0; q < 4; q++) accA[mt][nb][q] = 0.f;
    {
        unsigned a[2][4];
#pragma unroll
        for (int kk = 0; kk < 10; kk++) {
#pragma unroll
            for (int mt = 0; mt < 2; mt++) {
                int row = warp_m * 32 + mt * 16 + g;
                const char* base = pA + row * (SA2 * 2) + kk * 32 + 4 * t;
                a[mt][0] = *(const unsigned*)(base);
                a[mt][1] = *(const unsigned*)(base + 8 * (SA2 * 2));
                a[mt][2] = *(const unsigned*)(base + 16);
                a[mt][3] = *(const unsigned*)(base + 8 * (SA2 * 2) + 16);
            }
#pragma unroll
            for (int nb = 0; nb < 8; nb++) {
                uint2 b = sWu[(kk * 16 + warp_n * 8 + nb) * 32 + lane];
                mma_f16(accA[0][nb], a[0], b);
                mma_f16(accA[1][nb], a[1], b);
            }
        }
    }

    // ---- attention epilogue: logit = relu(h)·Wa2 + ba2 ----
    {
        float s00 = 0.f, s01 = 0.f, s10 = 0.f, s11 = 0.f;   // [mt][row-half]
#pragma unroll
        for (int nb = 0; nb < 8; nb++) {
            int c = warp_n * 64 + nb * 8 + 2 * t;
            float b0 = __ldg(ba1 + c), b1 = __ldg(ba1 + c + 1);
            float w0 = __ldg(Wa2 + c), w1 = __ldg(Wa2 + c + 1);
            s00 += fmaxf(accA[0][nb][0] + b0, 0.f) * w0 + fmaxf(accA[0][nb][1] + b1, 0.f) * w1;
            s01 += fmaxf(accA[0][nb][2] + b0, 0.f) * w0 + fmaxf(accA[0][nb][3] + b1, 0.f) * w1;
            s10 += fmaxf(accA[1][nb][0] + b0, 0.f) * w0 + fmaxf(accA[1][nb][1] + b1, 0.f) * w1;
            s11 += fmaxf(accA[1][nb][2] + b0, 0.f) * w0 + fmaxf(accA[1][nb][3] + b1, 0.f) * w1;
        }
#pragma unroll
        for (int off = 1; off <= 2; off <<= 1) {
            s00 += __shfl_xor_sync(0xffffffffu, s00, off);
            s01 += __shfl_xor_sync(0xffffffffu, s01, off);
            s10 += __shfl_xor_sync(0xffffffffu, s10, off);
            s11 += __shfl_xor_sync(0xffffffffu, s11, off);
        }
        if (t == 0) {
            sLogit[warp_n][warp_m * 32 + g]      = s00;
            sLogit[warp_n][warp_m * 32 + 8 + g]  = s01;
            sLogit[warp_n][warp_m * 32 + 16 + g] = s10;
            sLogit[warp_n][warp_m * 32 + 24 + g] = s11;
        }
    }
    __syncthreads();   // all GEMM1 A-reads done; sLogit ready

    if (tid < 128) {
        int e = e0 + tid;
        if (e < E) g_logits[e] = sLogit[0][tid] + sLogit[1][tid] + __ldg(ba2);
    }

    // ---- hidden relu -> fp16 A2 tile (overwrites pA cols 0..127) ----
#pragma unroll
    for (int mt = 0; mt < 2; mt++)
#pragma unroll
        for (int nb = 0; nb < 8; nb++) {
            int c = warp_n * 64 + nb * 8 + 2 * t;
            float b0 = __ldg(be1 + c), b1 = __ldg(be1 + c + 1);
            int r0 = warp_m * 32 + mt * 16 + g;
            *(unsigned*)(pA + r0 * (SA2 * 2) + c * 2) =
                pack_h2(fmaxf(accE[mt][nb][0] + b0, 0.f), fmaxf(accE[mt][nb][1] + b1, 0.f));
            *(unsigned*)(pA + (r0 + 8) * (SA2 * 2) + c * 2) =
                pack_h2(fmaxf(accE[mt][nb][2] + b0, 0.f), fmaxf(accE[mt][nb][3] + b1, 0.f));
        }
    // stage We2 frags
    for (int i = tid; i < 4096 / 4; i += 256) ((uint4*)sW)[i] = ((const uint4*)g_W2e)[i];
    __syncthreads();

    // ---- GEMM2: hidden[128x128] x We2 -> uh_e ----
    {
        float accO[2][4][4];
#pragma unroll
        for (int mt = 0; mt < 2; mt++)
#pragma unroll
            for (int nb = 0; nb < 4; nb++)
#pragma unroll
                for (int q = 0; q < 4; q++) accO[mt][nb][q] = 0.f;
        unsigned a[2][4];
#pragma unroll
        for (int kk = 0; kk < 8; kk++) {
#pragma unroll
            for (int mt = 0; mt < 2; mt++) {
                int row = warp_m * 32 + mt * 16 + g;
                const char* base = pA + row * (SA2 * 2) + kk * 32 + 4 * t;
                a[mt][0] = *(const unsigned*)(base);
                a[mt][1] = *(const unsigned*)(base + 8 * (SA2 * 2));
                a[mt][2] = *(const unsigned*)(base + 16);
                a[mt][3] = *(const unsigned*)(base + 8 * (SA2 * 2) + 16);
            }
#pragma unroll
            for (int nb = 0; nb < 4; nb++) {
                uint2 b = sWu[(kk * 8 + warp_n * 4 + nb) * 32 + lane];
                mma_f16(accO[0][nb], a[0], b);
                mma_f16(accO[1][nb], a[1], b);
            }
        }
        // epilogue: + be2, store
#pragma unroll
        for (int mt = 0; mt < 2; mt++)
#pragma unroll
            for (int nb = 0; nb < 4; nb++) {
                int c = warp_n * 32 + nb * 8 + 2 * t;
                float b0 = __ldg(be2 + c), b1 = __ldg(be2 + c + 1);
                int r0 = warp_m * 32 + mt * 16 + g;
                int e = e0 + r0;
                if (e < E)
                    *(float2*)(uh_e + (size_t)e * 64 + c) =
                        make_float2(accO[mt][nb][0] + b0, accO[mt][nb][1] + b1);
                if (e + 8 < E)
                    *(float2*)(uh_e + (size_t)(e + 8) * 64 + c) =
                        make_float2(accO[mt][nb][2] + b0, accO[mt][nb][3] + b1);
            }
    }
}

// ---------------- node kernel (fp32 SIMT, unchanged) ------------------------
#define TILE 128
#define SWP  132
#define SW2P 68
template <int K>
__device__ __forceinline__ void gemm_8x8(const float* __restrict__ sAm, int lda,
                                         const float* __restrict__ sB, int ldb,
                                         int tx, int ty, float acc[8][8]) {
#pragma unroll
    for (int i = 0; i < 8; i++)
#pragma unroll
        for (int j = 0; j < 8; j++) acc[i][j] = 0.f;
#pragma unroll 2
    for (int k = 0; k < K; k++) {
        float a[8];
#pragma unroll
        for (int i = 0; i < 8; i++) a[i] = sAm[(ty * 8 + i) * lda + k];
        float4 b0 = *(const float4*)(sB + k * ldb + tx * 8);
        float4 b1 = *(const float4*)(sB + k * ldb + tx * 8 + 4);
        float b[8] = {b0.x, b0.y, b0.z, b0.w, b1.x, b1.y, b1.z, b1.w};
#pragma unroll
        for (int i = 0; i < 8; i++)
#pragma unroll
            for (int j = 0; j < 8; j++)
                acc[i][j] = fmaf(a[i], b[j], acc[i][j]);
    }
}

__global__ void __launch_bounds__(256, 1)
node_kernel(const float* __restrict__ nf,
            const float* __restrict__ Wn1, const float* __restrict__ bn1,
            const float* __restrict__ Wn2, const float* __restrict__ bn2,
            float* __restrict__ uh_n, int N)
{
    extern __shared__ float smem[];
    float* sIn  = smem;
    float* sW1  = smem + TILE * SWP;
    float* sHid = sW1;
    float* sW2  = sW1 + TILE * SWP;

    const int tid = threadIdx.x;
    const int tx = tid & 15, ty = tid >> 4;
    const int n0 = blockIdx.x * TILE;

    for (int idx = tid; idx < TILE * 32; idx += 256) {
        int ln = idx >> 5, q = idx & 31;
        int n = n0 + ln;
        float4 v = make_float4(0.f, 0.f, 0.f, 0.f);
        if (n < N)
            v = (q < 16) ? __ldg((const float4*)(g_agg + (size_t)n * 64) + q)
                         : __ldg((const float4*)(nf + (size_t)n * 64) + (q - 16));
        *(float4*)(sIn + ln * SWP + q * 4) = v;
    }
    for (int idx = tid; idx < 128 * 32; idx += 256) {
        int r = idx >> 5, c4 = idx & 31;
        *(float4*)(sW1 + r * SWP + c4 * 4) = __ldg((const float4*)Wn1 + idx);
    }
    __syncthreads();

    float acc[8][8];
    gemm_8x8<128>(sIn, SWP, sW1, SWP, tx, ty, acc);
    __syncthreads();

    {
        float4 bb0 = __ldg((const float4*)bn1 + tx * 2);
        float4 bb1 = __ldg((const float4*)bn1 + tx * 2 + 1);
        float bb[8] = {bb0.x, bb0.y, bb0.z, bb0.w, bb1.x, bb1.y, bb1.z, bb1.w};
#pragma unroll
        for (int i = 0; i < 8; i++)
#pragma unroll
            for (int j = 0; j < 8; j++)
                sHid[(ty * 8 + i) * SWP + tx * 8 + j] = fmaxf(acc[i][j] + bb[j], 0.f);
    }
    for (int idx = tid; idx < 128 * 16; idx += 256) {
        int r = idx >> 4, c4 = idx & 15;
        *(float4*)(sW2 + r * SW2P + c4 * 4) = __ldg((const float4*)Wn2 + idx);
    }
    __syncthreads();

    {
        float acc2[8][4];
#pragma unroll
        for (int i = 0; i < 8; i++)
#pragma unroll
            for (int j = 0; j < 4; j++) acc2[i][j] = 0.f;
#pragma unroll 4
        for (int k = 0; k < 128; k++) {
            float a[8];
#pragma unroll
            for (int i = 0; i < 8; i++) a[i] = sHid[(ty * 8 + i) * SWP + k];
            float4 b = *(const float4*)(sW2 + k * SW2P + tx * 4);
#pragma unroll
            for (int i = 0; i < 8; i++) {
                acc2[i][0] = fmaf(a[i], b.x, acc2[i][0]);
                acc2[i][1] = fmaf(a[i], b.y, acc2[i][1]);
                acc2[i][2] = fmaf(a[i], b.z, acc2[i][2]);
                acc2[i][3] = fmaf(a[i], b.w, acc2[i][3]);
            }
        }
        float4 b2 = __ldg((const float4*)bn2 + tx);
#pragma unroll
        for (int i = 0; i < 8; i++) {
            int n = n0 + ty * 8 + i;
            if (n < N) {
                float4 o = make_float4(acc2[i][0] + b2.x, acc2[i][1] + b2.y,
                                       acc2[i][2] + b2.z, acc2[i][3] + b2.w);
                *(float4*)(uh_n + (size_t)n * 64 + tx * 4) = o;
            }
        }
    }
}

// ---------------- softmax / aggregation kernels -----------------------------
__global__ void init_kernel(int N) {
    int t = blockIdx.x * blockDim.x + threadIdx.x;
    if (t < N * 64) g_agg[t] = 0.f;
    if (t < N) { g_denom[t] = 0.f; g_maxb[t] = 0u; }
}
__global__ void max_kernel(const int* __restrict__ dst, int E) {
    int t = blockIdx.x * blockDim.x + threadIdx.x;
    if (t < E) atomicMax(&g_maxb[dst[t]], ordenc(g_logits[t]));
}
__global__ void ex_kernel(const int* __restrict__ dst, int E) {
    int t = blockIdx.x * blockDim.x + threadIdx.x;
    if (t < E) {
        int d = dst[t];
        float m = orddec(g_maxb[d]);
        if (!isfinite(m)) m = 0.f;
        float ex = expf(g_logits[t] - m);
        g_ex[t] = ex;
        atomicAdd(&g_denom[d], ex);
    }
}
__global__ void agg_kernel(const int* __restrict__ dst, const float* __restrict__ uh_e, int E) {
    int t = blockIdx.x * blockDim.x + threadIdx.x;
    int e = t >> 4, lane = t & 15;
    if (e < E) {
        int d = dst[e];
        float attn = g_ex[e] / fmaxf(g_denom[d], 1e-38f);
        float4 u = __ldg((const float4*)(uh_e + (size_t)e * 64) + lane);
        float* p = g_agg + (size_t)d * 64 + lane * 4;
        atomicAdd(p + 0, u.x * attn);
        atomicAdd(p + 1, u.y * attn);
        atomicAdd(p + 2, u.z * attn);
        atomicAdd(p + 3, u.w * attn);
    }
}

// ---------------- launch -----------------------------------------------------
extern "C" void kernel_launch(void* const* d_in, const int* in_sizes, int n_in,
                              void* d_out, int out_size)
{
    const float* nf  = (const float*)d_in[0];
    const float* ef  = (const float*)d_in[1];
    const int*   src = (const int*)d_in[2];
    const int*   dst = (const int*)d_in[3];
    const float* We1 = (const float*)d_in[4];
    const float* be1 = (const float*)d_in[5];
    const float* We2 = (const float*)d_in[6];
    const float* be2 = (const float*)d_in[7];
    const float* Wa1 = (const float*)d_in[8];
    const float* ba1 = (const float*)d_in[9];
    const float* Wa2 = (const float*)d_in[10];
    const float* ba2 = (const float*)d_in[11];
    const float* Wn1 = (const float*)d_in[12];
    const float* bn1 = (const float*)d_in[13];
    const float* Wn2 = (const float*)d_in[14];
    const float* bn2 = (const float*)d_in[15];

    const int N = in_sizes[0] / 64;
    const int E = in_sizes[2];

    float* uh_n = (float*)d_out;
    float* uh_e = uh_n + (size_t)N * 64;

    const int EDGE_SMEM = A_BYTES + W_UINTS * 4;                                 // 83968
    const int NODE_SMEM = (TILE * SWP * 2 + TILE * SW2P) * (int)sizeof(float);   // 169984

    cudaFuncSetAttribute(edge_kernel, cudaFuncAttributeMaxDynamicSharedMemorySize, EDGE_SMEM);
    cudaFuncSetAttribute(node_kernel, cudaFuncAttributeMaxDynamicSharedMemorySize, NODE_SMEM);

    prep_kernel<<<(10240 + 4096 + 255) / 256, 256>>>(We1, Wa1, We2);
    init_kernel<<<(N * 64 + 255) / 256, 256>>>(N);
    edge_kernel<<<(E + 127) / 128, 256, EDGE_SMEM>>>(
        nf, ef, src, dst, be1, be2, ba1, Wa2, ba2, uh_e, E);
    max_kernel<<<(E + 255) / 256, 256>>>(dst, E);
    ex_kernel<<<(E + 255) / 256, 256>>>(dst, E);
    agg_kernel<<<(int)(((size_t)E * 16 + 255) / 256), 256>>>(dst, uh_e, E);
    node_kernel<<<(N + TILE - 1) / TILE, 256, NODE_SMEM>>>(
        nf, Wn1, bn1, Wn2, bn2, uh_n, N);
}